// round 2
// baseline (speedup 1.0000x reference)
#include <cuda_runtime.h>

// PatchAttentionLayer: linear (no-softmax) attention with BN'd 1x1 convs.
// Algebraic restructure: fold BN into affine maps A_t, c_t; use associativity
// so the N x N pixelMap never materializes. Only Gram(x) [per batch] and one
// 256x256 @ 256x4096 GEMM per batch are "big".
//
// Shapes: x [8, 256, 64*64], W [256,256], vectors [256].

#define CCH 256
#define BATCH 8
#define HWN 4096
#define EPS_BN 1e-5f
#define INV_NPOS (1.0f / 32768.0f)
#define SCALE 0.125f   // 64^-0.5

// ---- scratch (device globals; no allocation allowed) ----
__device__ float g_G[BATCH][CCH][CCH];    // per-batch Gram of x
__device__ float g_s[BATCH][CCH];         // per-batch channel sums of x
__device__ float g_mean[CCH];             // global mean of x per channel
__device__ float g_Cov[CCH][CCH];         // global covariance of x
__device__ float g_A[3][CCH][CCH];        // effective matrices: 0=q,1=k,2=v
__device__ float g_cvec[3][CCH];          // effective bias vectors
__device__ float g_T1[BATCH][CCH][CCH];   // G_b * Ak^T
__device__ float g_M[BATCH][CCH][CCH];    // V K^T (256x256)
__device__ float g_P[BATCH][CCH][CCH];    // scale * M_b * Aq
__device__ float g_d[BATCH][CCH];         // scale * M_b * cq
__device__ float g_uw[BATCH][2][CCH];     // 0: Av*s_b, 1: Ak*s_b

// ---- shared micro-kernel: 64x64 tile, 4x4 per thread, BK=16 ----
__device__ __forceinline__ void mma16(const float (*As)[65], const float (*Bs)[65],
                                      int ty, int tx, float acc[4][4]) {
#pragma unroll
    for (int kk = 0; kk < 16; kk++) {
        float a[4], b[4];
#pragma unroll
        for (int i = 0; i < 4; i++) a[i] = As[kk][ty * 4 + i];
#pragma unroll
        for (int j = 0; j < 4; j++) b[j] = Bs[kk][tx * 4 + j];
#pragma unroll
        for (int i = 0; i < 4; i++)
#pragma unroll
            for (int j = 0; j < 4; j++) acc[i][j] += a[i] * b[j];
    }
}

// ---- per-(b,c) sums of x over the 4096 positions ----
__global__ void sums_kernel(const float* __restrict__ x) {
    int c = blockIdx.x, b = blockIdx.y;
    const float* p = x + ((long)b * CCH + c) * HWN;
    float s = 0.f;
    for (int i = threadIdx.x; i < HWN; i += 256) s += p[i];
    __shared__ float sh[256];
    sh[threadIdx.x] = s;
    __syncthreads();
    for (int off = 128; off > 0; off >>= 1) {
        if (threadIdx.x < off) sh[threadIdx.x] += sh[threadIdx.x + off];
        __syncthreads();
    }
    if (threadIdx.x == 0) g_s[b][c] = sh[0];
}

// ---- per-batch Gram: G_b = X_b X_b^T (X_b is [256, 4096]) ----
__global__ void gram_kernel(const float* __restrict__ x) {
    int b = blockIdx.z;
    int rowBase = blockIdx.y * 64, colBase = blockIdx.x * 64;
    const float* X = x + (long)b * CCH * HWN;
    __shared__ float As[16][65], Bs[16][65];
    int t = threadIdx.x;
    int tx = t & 15, ty = t >> 4;
    int r = t >> 2, kseg = (t & 3) * 4;
    float acc[4][4] = {};
    for (int k0 = 0; k0 < HWN; k0 += 16) {
        float4 av = *(const float4*)(X + (long)(rowBase + r) * HWN + k0 + kseg);
        float4 bv = *(const float4*)(X + (long)(colBase + r) * HWN + k0 + kseg);
        As[kseg + 0][r] = av.x; As[kseg + 1][r] = av.y; As[kseg + 2][r] = av.z; As[kseg + 3][r] = av.w;
        Bs[kseg + 0][r] = bv.x; Bs[kseg + 1][r] = bv.y; Bs[kseg + 2][r] = bv.z; Bs[kseg + 3][r] = bv.w;
        __syncthreads();
        mma16(As, Bs, ty, tx, acc);
        __syncthreads();
    }
#pragma unroll
    for (int i = 0; i < 4; i++)
#pragma unroll
        for (int j = 0; j < 4; j++)
            g_G[b][rowBase + ty * 4 + i][colBase + tx * 4 + j] = acc[i][j];
}

// ---- global mean ----
__global__ void mean_kernel() {
    int c = threadIdx.x;
    float s = 0.f;
#pragma unroll
    for (int b = 0; b < BATCH; b++) s += g_s[b][c];
    g_mean[c] = s * INV_NPOS;
}

// ---- covariance: Cov = (sum_b G_b)/Npos - m m^T ----
__global__ void cov_kernel() {
    int c = blockIdx.x, c2 = threadIdx.x;
    float s = 0.f;
#pragma unroll
    for (int b = 0; b < BATCH; b++) s += g_G[b][c][c2];
    g_Cov[c][c2] = s * INV_NPOS - g_mean[c] * g_mean[c2];
}

// ---- fold BN into affine maps: A_t = diag(g*rsqrt(var+eps))*W, c_t ----
__global__ void proj_kernel(
    const float* __restrict__ Wq, const float* __restrict__ bq, const float* __restrict__ gq, const float* __restrict__ beq,
    const float* __restrict__ Wk, const float* __restrict__ bk, const float* __restrict__ gk, const float* __restrict__ bek,
    const float* __restrict__ Wv, const float* __restrict__ bv, const float* __restrict__ gv, const float* __restrict__ bev) {
    int o = blockIdx.x, tp = blockIdx.y;
    const float *W, *bb, *gg, *be;
    if (tp == 0) { W = Wq; bb = bq; gg = gq; be = beq; }
    else if (tp == 1) { W = Wk; bb = bk; gg = gk; be = bek; }
    else { W = Wv; bb = bv; gg = gv; be = bev; }
    __shared__ float ws[CCH];
    int t = threadIdx.x;
    ws[t] = W[o * CCH + t];
    __syncthreads();
    // thread t handles column c'=t: col = sum_c w_c * Cov[c][t]  (coalesced)
    float col = 0.f;
    for (int c = 0; c < CCH; c++) col += ws[c] * g_Cov[c][t];
    float vterm = col * ws[t];
    float muterm = ws[t] * g_mean[t];
    __shared__ float s1[256], s2[256];
    s1[t] = vterm; s2[t] = muterm;
    __syncthreads();
    for (int off = 128; off > 0; off >>= 1) {
        if (t < off) { s1[t] += s1[t + off]; s2[t] += s2[t + off]; }
        __syncthreads();
    }
    __shared__ float a_sh, c_sh;
    if (t == 0) {
        float var = s1[0];
        float mu = s2[0] + bb[o];
        float a = gg[o] * rsqrtf(var + EPS_BN);
        a_sh = a;
        c_sh = (bb[o] - mu) * a + be[o];
    }
    __syncthreads();
    g_A[tp][o][t] = a_sh * ws[t];
    if (t == 0) g_cvec[tp][o] = c_sh;
}

// ---- u_b = Av s_b ; w_b = Ak s_b ----
__global__ void uw_kernel() {
    int j = blockIdx.x;      // 0 -> Av (proj 2), 1 -> Ak (proj 1)
    int b = blockIdx.y;
    int proj = (j == 0) ? 2 : 1;
    __shared__ float sv[CCH];
    int t = threadIdx.x;
    sv[t] = g_s[b][t];
    __syncthreads();
    float acc = 0.f;
    for (int c = 0; c < CCH; c++) acc += g_A[proj][t][c] * sv[c];
    g_uw[b][j][t] = acc;
}

// ---- T1_b = G_b * Ak^T  (NT, K=256) ----
__global__ void t1_kernel() {
    int b = blockIdx.z;
    int rowBase = blockIdx.y * 64, colBase = blockIdx.x * 64;
    __shared__ float As[16][65], Bs[16][65];
    int t = threadIdx.x;
    int tx = t & 15, ty = t >> 4;
    int r = t >> 2, kseg = (t & 3) * 4;
    float acc[4][4] = {};
    const float* A = &g_G[b][0][0];
    const float* B = &g_A[1][0][0];
    for (int k0 = 0; k0 < CCH; k0 += 16) {
        float4 av = *(const float4*)(A + (rowBase + r) * CCH + k0 + kseg);
        float4 bv = *(const float4*)(B + (colBase + r) * CCH + k0 + kseg);
        As[kseg + 0][r] = av.x; As[kseg + 1][r] = av.y; As[kseg + 2][r] = av.z; As[kseg + 3][r] = av.w;
        Bs[kseg + 0][r] = bv.x; Bs[kseg + 1][r] = bv.y; Bs[kseg + 2][r] = bv.z; Bs[kseg + 3][r] = bv.w;
        __syncthreads();
        mma16(As, Bs, ty, tx, acc);
        __syncthreads();
    }
#pragma unroll
    for (int i = 0; i < 4; i++)
#pragma unroll
        for (int j = 0; j < 4; j++)
            g_T1[b][rowBase + ty * 4 + i][colBase + tx * 4 + j] = acc[i][j];
}

// ---- M_b = Av * T1_b + rank-1 corrections  (NN, K=256) ----
__global__ void m_kernel() {
    int b = blockIdx.z;
    int rowBase = blockIdx.y * 64, colBase = blockIdx.x * 64;
    __shared__ float As[16][65], Bs[16][65];
    int t = threadIdx.x;
    int tx = t & 15, ty = t >> 4;
    int ar = t >> 2, akseg = (t & 3) * 4;
    int bkk = t >> 4, bcc = (t & 15) * 4;
    float acc[4][4] = {};
    const float* A = &g_A[2][0][0];   // Av [ov][c]
    const float* B = &g_T1[b][0][0];  // [c][ok]
    for (int k0 = 0; k0 < CCH; k0 += 16) {
        float4 av = *(const float4*)(A + (rowBase + ar) * CCH + k0 + akseg);
        float4 bv = *(const float4*)(B + (k0 + bkk) * CCH + colBase + bcc);
        As[akseg + 0][ar] = av.x; As[akseg + 1][ar] = av.y; As[akseg + 2][ar] = av.z; As[akseg + 3][ar] = av.w;
        Bs[bkk][bcc + 0] = bv.x; Bs[bkk][bcc + 1] = bv.y; Bs[bkk][bcc + 2] = bv.z; Bs[bkk][bcc + 3] = bv.w;
        __syncthreads();
        mma16(As, Bs, ty, tx, acc);
        __syncthreads();
    }
#pragma unroll
    for (int i = 0; i < 4; i++) {
        int ri = rowBase + ty * 4 + i;
        float u = g_uw[b][0][ri];
        float cv = g_cvec[2][ri];
#pragma unroll
        for (int j = 0; j < 4; j++) {
            int cj = colBase + tx * 4 + j;
            float ck = g_cvec[1][cj];
            float w = g_uw[b][1][cj];
            g_M[b][ri][cj] = acc[i][j] + u * ck + cv * w + 4096.0f * cv * ck;
        }
    }
}

// ---- P_b = scale * M_b * Aq  (NN, K=256) ----
__global__ void p_kernel() {
    int b = blockIdx.z;
    int rowBase = blockIdx.y * 64, colBase = blockIdx.x * 64;
    __shared__ float As[16][65], Bs[16][65];
    int t = threadIdx.x;
    int tx = t & 15, ty = t >> 4;
    int ar = t >> 2, akseg = (t & 3) * 4;
    int bkk = t >> 4, bcc = (t & 15) * 4;
    float acc[4][4] = {};
    const float* A = &g_M[b][0][0];   // [ov][oq]
    const float* B = &g_A[0][0][0];   // Aq [oq][cq]
    for (int k0 = 0; k0 < CCH; k0 += 16) {
        float4 av = *(const float4*)(A + (rowBase + ar) * CCH + k0 + akseg);
        float4 bv = *(const float4*)(B + (k0 + bkk) * CCH + colBase + bcc);
        As[akseg + 0][ar] = av.x; As[akseg + 1][ar] = av.y; As[akseg + 2][ar] = av.z; As[akseg + 3][ar] = av.w;
        Bs[bkk][bcc + 0] = bv.x; Bs[bkk][bcc + 1] = bv.y; Bs[bkk][bcc + 2] = bv.z; Bs[bkk][bcc + 3] = bv.w;
        __syncthreads();
        mma16(As, Bs, ty, tx, acc);
        __syncthreads();
    }
#pragma unroll
    for (int i = 0; i < 4; i++)
#pragma unroll
        for (int j = 0; j < 4; j++)
            g_P[b][rowBase + ty * 4 + i][colBase + tx * 4 + j] = acc[i][j] * SCALE;
}

// ---- d_b = scale * M_b * cq ----
__global__ void d_kernel() {
    int b = blockIdx.x;
    int t = threadIdx.x;
    __shared__ float cq[CCH];
    cq[t] = g_cvec[0][t];
    __syncthreads();
    float acc = 0.f;
    for (int c = 0; c < CCH; c++) acc += g_M[b][t][c] * cq[c];
    g_d[b][t] = acc * SCALE;
}

// ---- out[b] = P_b * x_b + d_b  (NN, K=256, N=4096) ----
__global__ void out_kernel(const float* __restrict__ x, float* __restrict__ out) {
    int b = blockIdx.z;
    int rowBase = blockIdx.y * 64, colBase = blockIdx.x * 64;
    __shared__ float As[16][65], Bs[16][65];
    int t = threadIdx.x;
    int tx = t & 15, ty = t >> 4;
    int ar = t >> 2, akseg = (t & 3) * 4;
    int bkk = t >> 4, bcc = (t & 15) * 4;
    float acc[4][4] = {};
    const float* A = &g_P[b][0][0];                 // [c][c'] lda=256
    const float* B = x + (long)b * CCH * HWN;       // [c'][p] ldb=4096
    for (int k0 = 0; k0 < CCH; k0 += 16) {
        float4 av = *(const float4*)(A + (rowBase + ar) * CCH + k0 + akseg);
        float4 bv = *(const float4*)(B + (long)(k0 + bkk) * HWN + colBase + bcc);
        As[akseg + 0][ar] = av.x; As[akseg + 1][ar] = av.y; As[akseg + 2][ar] = av.z; As[akseg + 3][ar] = av.w;
        Bs[bkk][bcc + 0] = bv.x; Bs[bkk][bcc + 1] = bv.y; Bs[bkk][bcc + 2] = bv.z; Bs[bkk][bcc + 3] = bv.w;
        __syncthreads();
        mma16(As, Bs, ty, tx, acc);
        __syncthreads();
    }
    float* O = out + (long)b * CCH * HWN;
#pragma unroll
    for (int i = 0; i < 4; i++) {
        int ri = rowBase + ty * 4 + i;
        float dd = g_d[b][ri];
#pragma unroll
        for (int j = 0; j < 4; j++) {
            int cj = colBase + tx * 4 + j;
            O[(long)ri * HWN + cj] = acc[i][j] + dd;
        }
    }
}

extern "C" void kernel_launch(void* const* d_in, const int* in_sizes, int n_in,
                              void* d_out, int out_size) {
    const float* x = (const float*)d_in[0];

    sums_kernel<<<dim3(CCH, BATCH), 256>>>(x);
    gram_kernel<<<dim3(4, 4, BATCH), 256>>>(x);
    mean_kernel<<<1, 256>>>();
    cov_kernel<<<CCH, 256>>>();
    proj_kernel<<<dim3(CCH, 3), 256>>>(
        (const float*)d_in[1], (const float*)d_in[2], (const float*)d_in[3], (const float*)d_in[4],
        (const float*)d_in[5], (const float*)d_in[6], (const float*)d_in[7], (const float*)d_in[8],
        (const float*)d_in[9], (const float*)d_in[10], (const float*)d_in[11], (const float*)d_in[12]);
    uw_kernel<<<dim3(2, BATCH), 256>>>();
    t1_kernel<<<dim3(4, 4, BATCH), 256>>>();
    m_kernel<<<dim3(4, 4, BATCH), 256>>>();
    p_kernel<<<dim3(4, 4, BATCH), 256>>>();
    d_kernel<<<BATCH, 256>>>();
    out_kernel<<<dim3(64, 4, BATCH), 256>>>(x, (float*)d_out);
}

// round 4
// speedup vs baseline: 2.2143x; 2.2143x over previous
#include <cuda_runtime.h>
#include <cuda_bf16.h>
#include <cstdint>

// PatchAttentionLayer on GB300 (sm_103 baseline PTX path — no tcgen05).
// BN folded into affine maps; attention via associativity (no NxN map).
// Big GEMMs on mma.sync bf16 (hi/lo split for fp32-class accuracy).

#define CCH 256
#define BATCH 8
#define HWN 4096
#define EPS_BN 1e-5f
#define INV_NPOS (1.0f / 32768.0f)
#define SCALE 0.125f

// ================= device scratch =================
__device__ __nv_bfloat16 g_xh[BATCH][CCH][HWN];   // hi split, [c][p]
__device__ __nv_bfloat16 g_xl[BATCH][CCH][HWN];   // lo split, [c][p]
__device__ float g_S1p[4][BATCH][CCH][CCH];       // split-K partials of Xh Xh^T
__device__ float g_S2p[4][BATCH][CCH][CCH];       // split-K partials of Xh Xl^T
__device__ float g_s[BATCH][CCH];
__device__ float g_mean[CCH];
__device__ float g_Cov[CCH][CCH];
__device__ float g_A[3][CCH][CCH];
__device__ float g_cvec[3][CCH];
__device__ float g_G[BATCH][CCH][CCH];
__device__ float g_T1[BATCH][CCH][CCH];
__device__ float g_M[BATCH][CCH][CCH];
__device__ float g_P[BATCH][CCH][CCH];
__device__ float g_d[BATCH][CCH];
__device__ float g_uw[BATCH][2][CCH];
__device__ __nv_bfloat16 g_Ph[BATCH][CCH][CCH];
__device__ __nv_bfloat16 g_Pl[BATCH][CCH][CCH];

// ================= mma helpers (sm_80+ baseline PTX) =================
__device__ __forceinline__ uint32_t smem_u32(const void* p) {
    uint32_t a;
    asm("{ .reg .u64 t; cvta.to.shared.u64 t, %1; cvt.u32.u64 %0, t; }" : "=r"(a) : "l"(p));
    return a;
}
__device__ __forceinline__ void ldsm4(uint32_t* r, uint32_t a) {
    asm volatile("ldmatrix.sync.aligned.m8n8.x4.shared.b16 {%0,%1,%2,%3}, [%4];"
                 : "=r"(r[0]), "=r"(r[1]), "=r"(r[2]), "=r"(r[3]) : "r"(a));
}
__device__ __forceinline__ void ldsm4t(uint32_t* r, uint32_t a) {
    asm volatile("ldmatrix.sync.aligned.m8n8.x4.trans.shared.b16 {%0,%1,%2,%3}, [%4];"
                 : "=r"(r[0]), "=r"(r[1]), "=r"(r[2]), "=r"(r[3]) : "r"(a));
}
__device__ __forceinline__ void mma_bf16(float* c, const uint32_t* a, const uint32_t* b) {
    asm volatile(
        "mma.sync.aligned.m16n8k16.row.col.f32.bf16.bf16.f32 "
        "{%0,%1,%2,%3},{%4,%5,%6,%7},{%8,%9},{%0,%1,%2,%3};"
        : "+f"(c[0]), "+f"(c[1]), "+f"(c[2]), "+f"(c[3])
        : "r"(a[0]), "r"(a[1]), "r"(a[2]), "r"(a[3]), "r"(b[0]), "r"(b[1]));
}
#define CPA16(dst, src) asm volatile("cp.async.cg.shared.global [%0], [%1], 16;" :: "r"(dst), "l"(src))
#define CPA_COMMIT()    asm volatile("cp.async.commit_group;")
#define CPA_WAIT1()     asm volatile("cp.async.wait_group 1;")
#define CPA_WAIT0()     asm volatile("cp.async.wait_group 0;")

// ================= prep: fp32 -> hi/lo bf16 + per-(b,c) sums =================
__global__ __launch_bounds__(256) void prep_kernel(const float* __restrict__ x) {
    int c = blockIdx.x, b = blockIdx.y;
    const float4* src = (const float4*)(x + ((long)(b * CCH + c)) * HWN);
    __nv_bfloat162* dh = (__nv_bfloat162*)&g_xh[b][c][0];
    __nv_bfloat162* dl = (__nv_bfloat162*)&g_xl[b][c][0];
    float s = 0.f;
    for (int i = threadIdx.x; i < 1024; i += 256) {
        float4 v = src[i];
        s += (v.x + v.y) + (v.z + v.w);
        __nv_bfloat16 h0 = __float2bfloat16(v.x), h1 = __float2bfloat16(v.y);
        __nv_bfloat16 h2 = __float2bfloat16(v.z), h3 = __float2bfloat16(v.w);
        __nv_bfloat162 hh0; hh0.x = h0; hh0.y = h1;
        __nv_bfloat162 hh1; hh1.x = h2; hh1.y = h3;
        __nv_bfloat162 ll0, ll1;
        ll0.x = __float2bfloat16(v.x - __bfloat162float(h0));
        ll0.y = __float2bfloat16(v.y - __bfloat162float(h1));
        ll1.x = __float2bfloat16(v.z - __bfloat162float(h2));
        ll1.y = __float2bfloat16(v.w - __bfloat162float(h3));
        dh[2 * i] = hh0; dh[2 * i + 1] = hh1;
        dl[2 * i] = ll0; dl[2 * i + 1] = ll1;
    }
    __shared__ float sh[256];
    sh[threadIdx.x] = s;
    __syncthreads();
    for (int off = 128; off > 0; off >>= 1) {
        if (threadIdx.x < off) sh[threadIdx.x] += sh[threadIdx.x + off];
        __syncthreads();
    }
    if (threadIdx.x == 0) g_s[b][c] = sh[0];
}

// ================= gram via mma.sync: S1 = H H^T, S2 = H L^T =================
// grid: x = split(4)*2 + which, y = mtile*2 + ntile, z = batch. CTA 128x128, BK=32.
#define GPAD 40   // bf16 per smem row (32 data + 8 pad) -> 80B, conflict-free ldsm

__global__ __launch_bounds__(256) void gram_mma_kernel() {
    __shared__ __nv_bfloat16 sm[2][2][128 * GPAD];  // [buf][A=0/B=1]
    int t = threadIdx.x, lane = t & 31, wid = t >> 5;
    int split = blockIdx.x >> 1, which = blockIdx.x & 1;
    int mt = blockIdx.y >> 1, nt = blockIdx.y & 1, b = blockIdx.z;
    const __nv_bfloat16* Ag = &g_xh[b][mt * 128][0];
    const __nv_bfloat16* Bg = which ? &g_xl[b][nt * 128][0] : &g_xh[b][nt * 128][0];
    int k0 = split * 1024;
    int wm = (wid >> 2) * 64, wn = (wid & 3) * 32;
    uint32_t sA0 = smem_u32(&sm[0][0][0]), sB0 = smem_u32(&sm[0][1][0]);
    const uint32_t bufStride = 2 * 128 * GPAD * 2;  // bytes between buf0 and buf1

    float acc[4][4][4] = {};

    auto stage = [&](int buf, int kk) {
        uint32_t aBase = sA0 + buf * bufStride, bBase = sB0 + buf * bufStride;
#pragma unroll
        for (int i = t; i < 512; i += 256) {
            int r = i >> 2, c = i & 3;
            CPA16(aBase + r * 80 + c * 16, (const char*)(Ag + (long)r * HWN + kk + c * 8));
        }
#pragma unroll
        for (int i = t; i < 512; i += 256) {
            int r = i >> 2, c = i & 3;
            CPA16(bBase + r * 80 + c * 16, (const char*)(Bg + (long)r * HWN + kk + c * 8));
        }
    };

    stage(0, k0);
    CPA_COMMIT();
    const int S = 32;
    for (int s = 0; s < S; s++) {
        if (s + 1 < S) { stage((s + 1) & 1, k0 + (s + 1) * 32); CPA_COMMIT(); CPA_WAIT1(); }
        else CPA_WAIT0();
        __syncthreads();
        uint32_t aBase = sA0 + (s & 1) * bufStride, bBase = sB0 + (s & 1) * bufStride;
#pragma unroll
        for (int ks = 0; ks < 32; ks += 16) {
            uint32_t af[4][4], bf[4][2];
#pragma unroll
            for (int i = 0; i < 4; i++)
                ldsm4(af[i], aBase + (wm + i * 16 + (lane & 15)) * 80 + ks * 2 + (lane >> 4) * 16);
#pragma unroll
            for (int j = 0; j < 2; j++) {
                uint32_t r[4];
                ldsm4(r, bBase + (wn + j * 16 + (lane & 15)) * 80 + ks * 2 + (lane >> 4) * 16);
                bf[2 * j][0] = r[0]; bf[2 * j][1] = r[2];
                bf[2 * j + 1][0] = r[1]; bf[2 * j + 1][1] = r[3];
            }
#pragma unroll
            for (int i = 0; i < 4; i++)
#pragma unroll
                for (int j = 0; j < 4; j++) mma_bf16(acc[i][j], af[i], bf[j]);
        }
        __syncthreads();
    }

    float* dst = which ? &g_S2p[split][b][0][0] : &g_S1p[split][b][0][0];
#pragma unroll
    for (int i = 0; i < 4; i++) {
        int m = mt * 128 + wm + i * 16 + (lane >> 2);
#pragma unroll
        for (int j = 0; j < 4; j++) {
            int n = nt * 128 + wn + j * 8 + (lane & 3) * 2;
            *(float2*)(dst + (long)m * CCH + n) = make_float2(acc[i][j][0], acc[i][j][1]);
            *(float2*)(dst + (long)(m + 8) * CCH + n) = make_float2(acc[i][j][2], acc[i][j][3]);
        }
    }
}

// G[b] = sum_s (S1 + S2) + (sum_s S2)^T
__global__ __launch_bounds__(256) void reduceG_kernel() {
    __shared__ float tt[32][33];
    int jt = blockIdx.x * 32, it = blockIdx.y * 32, b = blockIdx.z;
    int lx = threadIdx.x & 31, ly = threadIdx.x >> 5;
    for (int r = ly; r < 32; r += 8) {
        float s = 0.f;
#pragma unroll
        for (int sp = 0; sp < 4; sp++) s += g_S2p[sp][b][jt + r][it + lx];
        tt[r][lx] = s;
    }
    __syncthreads();
    for (int r = ly; r < 32; r += 8) {
        float s = tt[lx][r];
#pragma unroll
        for (int sp = 0; sp < 4; sp++)
            s += g_S1p[sp][b][it + r][jt + lx] + g_S2p[sp][b][it + r][jt + lx];
        g_G[b][it + r][jt + lx] = s;
    }
}

// ================= glue (CUDA cores, fp32) =================
__global__ void mean_kernel() {
    int c = threadIdx.x;
    float s = 0.f;
#pragma unroll
    for (int b = 0; b < BATCH; b++) s += g_s[b][c];
    g_mean[c] = s * INV_NPOS;
}

__global__ void cov_kernel() {
    int c = blockIdx.x, c2 = threadIdx.x;
    float s = 0.f;
#pragma unroll
    for (int b = 0; b < BATCH; b++) s += g_G[b][c][c2];
    g_Cov[c][c2] = s * INV_NPOS - g_mean[c] * g_mean[c2];
}

__global__ void proj_kernel(
    const float* __restrict__ Wq, const float* __restrict__ bq, const float* __restrict__ gq, const float* __restrict__ beq,
    const float* __restrict__ Wk, const float* __restrict__ bk, const float* __restrict__ gk, const float* __restrict__ bek,
    const float* __restrict__ Wv, const float* __restrict__ bv, const float* __restrict__ gv, const float* __restrict__ bev) {
    int o = blockIdx.x, tp = blockIdx.y;
    const float *W, *bb, *gg, *be;
    if (tp == 0) { W = Wq; bb = bq; gg = gq; be = beq; }
    else if (tp == 1) { W = Wk; bb = bk; gg = gk; be = bek; }
    else { W = Wv; bb = bv; gg = gv; be = bev; }
    __shared__ float ws[CCH];
    int t = threadIdx.x;
    ws[t] = W[o * CCH + t];
    __syncthreads();
    float col = 0.f;
    for (int c = 0; c < CCH; c++) col += ws[c] * g_Cov[c][t];
    __shared__ float s1[256], s2[256];
    s1[t] = col * ws[t]; s2[t] = ws[t] * g_mean[t];
    __syncthreads();
    for (int off = 128; off > 0; off >>= 1) {
        if (t < off) { s1[t] += s1[t + off]; s2[t] += s2[t + off]; }
        __syncthreads();
    }
    __shared__ float a_sh, c_sh;
    if (t == 0) {
        float var = s1[0];
        float mu = s2[0] + bb[o];
        float a = gg[o] * rsqrtf(var + EPS_BN);
        a_sh = a;
        c_sh = (bb[o] - mu) * a + be[o];
    }
    __syncthreads();
    g_A[tp][o][t] = a_sh * ws[t];
    if (t == 0) g_cvec[tp][o] = c_sh;
}

__global__ void uw_kernel() {
    int j = blockIdx.x, b = blockIdx.y;
    int proj = (j == 0) ? 2 : 1;
    __shared__ float sv[CCH];
    int t = threadIdx.x;
    sv[t] = g_s[b][t];
    __syncthreads();
    float acc = 0.f;
    for (int c = 0; c < CCH; c++) acc += g_A[proj][t][c] * sv[c];
    g_uw[b][j][t] = acc;
}

__device__ __forceinline__ void mma16f(const float (*As)[65], const float (*Bs)[65],
                                       int ty, int tx, float acc[4][4]) {
#pragma unroll
    for (int kk = 0; kk < 16; kk++) {
        float a[4], b[4];
#pragma unroll
        for (int i = 0; i < 4; i++) a[i] = As[kk][ty * 4 + i];
#pragma unroll
        for (int j = 0; j < 4; j++) b[j] = Bs[kk][tx * 4 + j];
#pragma unroll
        for (int i = 0; i < 4; i++)
#pragma unroll
            for (int j = 0; j < 4; j++) acc[i][j] += a[i] * b[j];
    }
}

__global__ void t1_kernel() {
    int b = blockIdx.z;
    int rowBase = blockIdx.y * 64, colBase = blockIdx.x * 64;
    __shared__ float As[16][65], Bs[16][65];
    int t = threadIdx.x, tx = t & 15, ty = t >> 4;
    int r = t >> 2, kseg = (t & 3) * 4;
    float acc[4][4] = {};
    const float* A = &g_G[b][0][0];
    const float* B = &g_A[1][0][0];
    for (int k0 = 0; k0 < CCH; k0 += 16) {
        float4 av = *(const float4*)(A + (rowBase + r) * CCH + k0 + kseg);
        float4 bv = *(const float4*)(B + (colBase + r) * CCH + k0 + kseg);
        As[kseg + 0][r] = av.x; As[kseg + 1][r] = av.y; As[kseg + 2][r] = av.z; As[kseg + 3][r] = av.w;
        Bs[kseg + 0][r] = bv.x; Bs[kseg + 1][r] = bv.y; Bs[kseg + 2][r] = bv.z; Bs[kseg + 3][r] = bv.w;
        __syncthreads();
        mma16f(As, Bs, ty, tx, acc);
        __syncthreads();
    }
#pragma unroll
    for (int i = 0; i < 4; i++)
#pragma unroll
        for (int j = 0; j < 4; j++)
            g_T1[b][rowBase + ty * 4 + i][colBase + tx * 4 + j] = acc[i][j];
}

__global__ void m_kernel() {
    int b = blockIdx.z;
    int rowBase = blockIdx.y * 64, colBase = blockIdx.x * 64;
    __shared__ float As[16][65], Bs[16][65];
    int t = threadIdx.x, tx = t & 15, ty = t >> 4;
    int ar = t >> 2, akseg = (t & 3) * 4;
    int bkk = t >> 4, bcc = (t & 15) * 4;
    float acc[4][4] = {};
    const float* A = &g_A[2][0][0];
    const float* B = &g_T1[b][0][0];
    for (int k0 = 0; k0 < CCH; k0 += 16) {
        float4 av = *(const float4*)(A + (rowBase + ar) * CCH + k0 + akseg);
        float4 bv = *(const float4*)(B + (k0 + bkk) * CCH + colBase + bcc);
        As[akseg + 0][ar] = av.x; As[akseg + 1][ar] = av.y; As[akseg + 2][ar] = av.z; As[akseg + 3][ar] = av.w;
        Bs[bkk][bcc + 0] = bv.x; Bs[bkk][bcc + 1] = bv.y; Bs[bkk][bcc + 2] = bv.z; Bs[bkk][bcc + 3] = bv.w;
        __syncthreads();
        mma16f(As, Bs, ty, tx, acc);
        __syncthreads();
    }
#pragma unroll
    for (int i = 0; i < 4; i++) {
        int ri = rowBase + ty * 4 + i;
        float u = g_uw[b][0][ri], cv = g_cvec[2][ri];
#pragma unroll
        for (int j = 0; j < 4; j++) {
            int cj = colBase + tx * 4 + j;
            g_M[b][ri][cj] = acc[i][j] + u * g_cvec[1][cj] + cv * g_uw[b][1][cj]
                           + 4096.0f * cv * g_cvec[1][cj];
        }
    }
}

__global__ void p_kernel() {
    int b = blockIdx.z;
    int rowBase = blockIdx.y * 64, colBase = blockIdx.x * 64;
    __shared__ float As[16][65], Bs[16][65];
    int t = threadIdx.x, tx = t & 15, ty = t >> 4;
    int ar = t >> 2, akseg = (t & 3) * 4;
    int bkk = t >> 4, bcc = (t & 15) * 4;
    float acc[4][4] = {};
    const float* A = &g_M[b][0][0];
    const float* B = &g_A[0][0][0];
    for (int k0 = 0; k0 < CCH; k0 += 16) {
        float4 av = *(const float4*)(A + (rowBase + ar) * CCH + k0 + akseg);
        float4 bv = *(const float4*)(B + (k0 + bkk) * CCH + colBase + bcc);
        As[akseg + 0][ar] = av.x; As[akseg + 1][ar] = av.y; As[akseg + 2][ar] = av.z; As[akseg + 3][ar] = av.w;
        Bs[bkk][bcc + 0] = bv.x; Bs[bkk][bcc + 1] = bv.y; Bs[bkk][bcc + 2] = bv.z; Bs[bkk][bcc + 3] = bv.w;
        __syncthreads();
        mma16f(As, Bs, ty, tx, acc);
        __syncthreads();
    }
#pragma unroll
    for (int i = 0; i < 4; i++)
#pragma unroll
        for (int j = 0; j < 4; j++)
            g_P[b][rowBase + ty * 4 + i][colBase + tx * 4 + j] = acc[i][j] * SCALE;
}

__global__ void d_kernel() {
    int b = blockIdx.x, t = threadIdx.x;
    __shared__ float cq[CCH];
    cq[t] = g_cvec[0][t];
    __syncthreads();
    float acc = 0.f;
    for (int c = 0; c < CCH; c++) acc += g_M[b][t][c] * cq[c];
    g_d[b][t] = acc * SCALE;
}

__global__ void pconv_kernel() {
    int b = blockIdx.y;
    int i = blockIdx.x * 256 + threadIdx.x;
    float v = (&g_P[b][0][0])[i];
    __nv_bfloat16 h = __float2bfloat16(v);
    __nv_bfloat16 l = __float2bfloat16(v - __bfloat162float(h));
    (&g_Ph[b][0][0])[i] = h;
    (&g_Pl[b][0][0])[i] = l;
}

// ================= out via mma.sync: out = Ph Xh + Ph Xl + Pl Xh =================
// grid: x = p-tile (32), y = m-tile (2), z = batch. CTA 128(M=c) x 128(N=p), K=256, BK=32.
#define OB_STRIDE 272   // bytes per B smem row (128 bf16 + 8 pad)
#define OU_AH 0
#define OU_AL 10240
#define OU_BH 20480
#define OU_BL (20480 + 32 * OB_STRIDE)
#define OU_BUF (20480 + 2 * 32 * OB_STRIDE)   // 37888
#define OU_SMEM (2 * OU_BUF)                  // 75776

__global__ __launch_bounds__(256) void out_mma_kernel(float* __restrict__ out) {
    extern __shared__ char smem[];
    uint32_t sb = smem_u32(smem);
    int t = threadIdx.x, lane = t & 31, wid = t >> 5;
    int pt = blockIdx.x, mt = blockIdx.y, b = blockIdx.z;
    int wm = (wid >> 2) * 64, wn = (wid & 3) * 32;
    const __nv_bfloat16* Ah = &g_Ph[b][mt * 128][0];
    const __nv_bfloat16* Al = &g_Pl[b][mt * 128][0];
    const __nv_bfloat16* Bh = &g_xh[b][0][pt * 128];
    const __nv_bfloat16* Bl = &g_xl[b][0][pt * 128];

    float acc[4][4][4] = {};

    auto stage = [&](int buf, int kk) {
        uint32_t base = sb + buf * OU_BUF;
#pragma unroll
        for (int i = t; i < 512; i += 256) {   // A tiles: 128 rows x 4 chunks, h then l
            int r = i >> 2, c = i & 3;
            CPA16(base + OU_AH + r * 80 + c * 16, (const char*)(Ah + (long)r * CCH + kk + c * 8));
            CPA16(base + OU_AL + r * 80 + c * 16, (const char*)(Al + (long)r * CCH + kk + c * 8));
        }
#pragma unroll
        for (int i = t; i < 512; i += 256) {   // B tiles: 32 rows (k=c') x 16 chunks (n=p)
            int r = i >> 4, c = i & 15;
            CPA16(base + OU_BH + r * OB_STRIDE + c * 16, (const char*)(Bh + (long)(kk + r) * HWN + c * 8));
            CPA16(base + OU_BL + r * OB_STRIDE + c * 16, (const char*)(Bl + (long)(kk + r) * HWN + c * 8));
        }
    };

    stage(0, 0);
    CPA_COMMIT();
    const int S = 8;  // K=256 / 32
    for (int s = 0; s < S; s++) {
        if (s + 1 < S) { stage((s + 1) & 1, (s + 1) * 32); CPA_COMMIT(); CPA_WAIT1(); }
        else CPA_WAIT0();
        __syncthreads();
        uint32_t base = sb + (s & 1) * OU_BUF;
#pragma unroll
        for (int ks = 0; ks < 32; ks += 16) {
            uint32_t afh[4][4], afl[4][4], bfh[4][2], bfl[4][2];
#pragma unroll
            for (int i = 0; i < 4; i++) {
                uint32_t ao = (wm + i * 16 + (lane & 15)) * 80 + ks * 2 + (lane >> 4) * 16;
                ldsm4(afh[i], base + OU_AH + ao);
                ldsm4(afl[i], base + OU_AL + ao);
            }
#pragma unroll
            for (int j = 0; j < 2; j++) {
                uint32_t bo = (ks + (lane & 15)) * OB_STRIDE + (wn + j * 16 + (lane >> 4) * 8) * 2;
                uint32_t r[4];
                ldsm4t(r, base + OU_BH + bo);
                bfh[2 * j][0] = r[0]; bfh[2 * j][1] = r[1];
                bfh[2 * j + 1][0] = r[2]; bfh[2 * j + 1][1] = r[3];
                ldsm4t(r, base + OU_BL + bo);
                bfl[2 * j][0] = r[0]; bfl[2 * j][1] = r[1];
                bfl[2 * j + 1][0] = r[2]; bfl[2 * j + 1][1] = r[3];
            }
#pragma unroll
            for (int i = 0; i < 4; i++)
#pragma unroll
                for (int j = 0; j < 4; j++) {
                    mma_bf16(acc[i][j], afh[i], bfh[j]);
                    mma_bf16(acc[i][j], afh[i], bfl[j]);
                    mma_bf16(acc[i][j], afl[i], bfh[j]);
                }
        }
        __syncthreads();
    }

#pragma unroll
    for (int i = 0; i < 4; i++) {
        int m = mt * 128 + wm + i * 16 + (lane >> 2);
        float d0 = g_d[b][m], d1 = g_d[b][m + 8];
        float* O0 = out + ((long)(b * CCH + m)) * HWN + pt * 128;
        float* O1 = O0 + 8L * HWN;
#pragma unroll
        for (int j = 0; j < 4; j++) {
            int n = wn + j * 8 + (lane & 3) * 2;
            *(float2*)(O0 + n) = make_float2(acc[i][j][0] + d0, acc[i][j][1] + d0);
            *(float2*)(O1 + n) = make_float2(acc[i][j][2] + d1, acc[i][j][3] + d1);
        }
    }
}

// ================= launch =================
extern "C" void kernel_launch(void* const* d_in, const int* in_sizes, int n_in,
                              void* d_out, int out_size) {
    const float* x = (const float*)d_in[0];

    static bool attr_done = false;
    if (!attr_done) {
        cudaFuncSetAttribute(out_mma_kernel, cudaFuncAttributeMaxDynamicSharedMemorySize, OU_SMEM);
        attr_done = true;
    }

    prep_kernel<<<dim3(CCH, BATCH), 256>>>(x);
    gram_mma_kernel<<<dim3(8, 4, BATCH), 256>>>();
    reduceG_kernel<<<dim3(8, 8, BATCH), 256>>>();
    mean_kernel<<<1, 256>>>();
    cov_kernel<<<CCH, 256>>>();
    proj_kernel<<<dim3(CCH, 3), 256>>>(
        (const float*)d_in[1], (const float*)d_in[2], (const float*)d_in[3], (const float*)d_in[4],
        (const float*)d_in[5], (const float*)d_in[6], (const float*)d_in[7], (const float*)d_in[8],
        (const float*)d_in[9], (const float*)d_in[10], (const float*)d_in[11], (const float*)d_in[12]);
    uw_kernel<<<dim3(2, BATCH), 256>>>();
    t1_kernel<<<dim3(4, 4, BATCH), 256>>>();
    m_kernel<<<dim3(4, 4, BATCH), 256>>>();
    p_kernel<<<dim3(4, 4, BATCH), 256>>>();
    d_kernel<<<BATCH, 256>>>();
    pconv_kernel<<<dim3(256, BATCH), 256>>>();
    out_mma_kernel<<<dim3(32, 2, BATCH), 256, OU_SMEM>>>((float*)d_out);
}

// round 5
// speedup vs baseline: 2.7376x; 1.2364x over previous
#include <cuda_runtime.h>
#include <cuda_bf16.h>
#include <cstdint>

// PatchAttentionLayer on GB300 (sm_103 baseline PTX path — no tcgen05).
// BN folded into affine maps; attention via associativity (no NxN map).
// Big GEMMs on mma.sync bf16 (hi/lo split for fp32-class accuracy).
// R5: fused glue (9 launches), gram S1+S2 share A tiles (128 CTAs = 1 wave).

#define CCH 256
#define BATCH 8
#define HWN 4096
#define EPS_BN 1e-5f
#define INV_NPOS (1.0f / 32768.0f)
#define SCALE 0.125f

// ================= device scratch =================
__device__ __nv_bfloat16 g_xh[BATCH][CCH][HWN];   // hi split, [c][p]
__device__ __nv_bfloat16 g_xl[BATCH][CCH][HWN];   // lo split, [c][p]
__device__ float g_S1p[4][BATCH][CCH][CCH];       // split-K partials of Xh Xh^T
__device__ float g_S2p[4][BATCH][CCH][CCH];       // split-K partials of Xh Xl^T
__device__ float g_s[BATCH][CCH];
__device__ float g_mean[CCH];
__device__ float g_Cov[CCH][CCH];
__device__ float g_A[3][CCH][CCH];
__device__ float g_cvec[3][CCH];
__device__ float g_G[BATCH][CCH][CCH];
__device__ float g_T1[BATCH][CCH][CCH];
__device__ float g_M[BATCH][CCH][CCH];
__device__ float g_d[BATCH][CCH];
__device__ __nv_bfloat16 g_Ph[BATCH][CCH][CCH];
__device__ __nv_bfloat16 g_Pl[BATCH][CCH][CCH];

// ================= mma helpers (sm_80+ baseline PTX) =================
__device__ __forceinline__ uint32_t smem_u32(const void* p) {
    uint32_t a;
    asm("{ .reg .u64 t; cvta.to.shared.u64 t, %1; cvt.u32.u64 %0, t; }" : "=r"(a) : "l"(p));
    return a;
}
__device__ __forceinline__ void ldsm4(uint32_t* r, uint32_t a) {
    asm volatile("ldmatrix.sync.aligned.m8n8.x4.shared.b16 {%0,%1,%2,%3}, [%4];"
                 : "=r"(r[0]), "=r"(r[1]), "=r"(r[2]), "=r"(r[3]) : "r"(a));
}
__device__ __forceinline__ void ldsm4t(uint32_t* r, uint32_t a) {
    asm volatile("ldmatrix.sync.aligned.m8n8.x4.trans.shared.b16 {%0,%1,%2,%3}, [%4];"
                 : "=r"(r[0]), "=r"(r[1]), "=r"(r[2]), "=r"(r[3]) : "r"(a));
}
__device__ __forceinline__ void mma_bf16(float* c, const uint32_t* a, const uint32_t* b) {
    asm volatile(
        "mma.sync.aligned.m16n8k16.row.col.f32.bf16.bf16.f32 "
        "{%0,%1,%2,%3},{%4,%5,%6,%7},{%8,%9},{%0,%1,%2,%3};"
        : "+f"(c[0]), "+f"(c[1]), "+f"(c[2]), "+f"(c[3])
        : "r"(a[0]), "r"(a[1]), "r"(a[2]), "r"(a[3]), "r"(b[0]), "r"(b[1]));
}
#define CPA16(dst, src) asm volatile("cp.async.cg.shared.global [%0], [%1], 16;" :: "r"(dst), "l"(src))
#define CPA_COMMIT()    asm volatile("cp.async.commit_group;")
#define CPA_WAIT1()     asm volatile("cp.async.wait_group 1;")
#define CPA_WAIT0()     asm volatile("cp.async.wait_group 0;")

// ================= prep: fp32 -> hi/lo bf16 + per-(b,c) sums =================
__global__ __launch_bounds__(256) void prep_kernel(const float* __restrict__ x) {
    int c = blockIdx.x, b = blockIdx.y;
    const float4* src = (const float4*)(x + ((long)(b * CCH + c)) * HWN);
    __nv_bfloat162* dh = (__nv_bfloat162*)&g_xh[b][c][0];
    __nv_bfloat162* dl = (__nv_bfloat162*)&g_xl[b][c][0];
    float s = 0.f;
    for (int i = threadIdx.x; i < 1024; i += 256) {
        float4 v = src[i];
        s += (v.x + v.y) + (v.z + v.w);
        __nv_bfloat16 h0 = __float2bfloat16(v.x), h1 = __float2bfloat16(v.y);
        __nv_bfloat16 h2 = __float2bfloat16(v.z), h3 = __float2bfloat16(v.w);
        __nv_bfloat162 hh0; hh0.x = h0; hh0.y = h1;
        __nv_bfloat162 hh1; hh1.x = h2; hh1.y = h3;
        __nv_bfloat162 ll0, ll1;
        ll0.x = __float2bfloat16(v.x - __bfloat162float(h0));
        ll0.y = __float2bfloat16(v.y - __bfloat162float(h1));
        ll1.x = __float2bfloat16(v.z - __bfloat162float(h2));
        ll1.y = __float2bfloat16(v.w - __bfloat162float(h3));
        dh[2 * i] = hh0; dh[2 * i + 1] = hh1;
        dl[2 * i] = ll0; dl[2 * i + 1] = ll1;
    }
    __shared__ float sh[256];
    sh[threadIdx.x] = s;
    __syncthreads();
    for (int off = 128; off > 0; off >>= 1) {
        if (threadIdx.x < off) sh[threadIdx.x] += sh[threadIdx.x + off];
        __syncthreads();
    }
    if (threadIdx.x == 0) g_s[b][c] = sh[0];
}

// ================= gram via mma.sync: S1 = H H^T and S2 = H L^T fused =================
// grid: x = split(4), y = tile(2x2), z = batch. CTA 128x128, 512 threads.
// Warps 0-7 -> S1 (B = H), warps 8-15 -> S2 (B = L); A staged once, shared.
#define GR_TILE 10240                 // 128 rows * 80 B (32 bf16 + 8 pad)
#define GR_BUF  (3 * GR_TILE)         // A, Bh, Bl
#define GR_SMEM (2 * GR_BUF)          // double buffered: 61440 B

__global__ __launch_bounds__(512) void gram_mma_kernel() {
    extern __shared__ char smem[];
    uint32_t sb = smem_u32(smem);
    int t = threadIdx.x, lane = t & 31, wid = t >> 5;
    int split = blockIdx.x, b = blockIdx.z;
    int mt = blockIdx.y >> 1, nt = blockIdx.y & 1;
    const __nv_bfloat16* Ag  = &g_xh[b][mt * 128][0];
    const __nv_bfloat16* BgH = &g_xh[b][nt * 128][0];
    const __nv_bfloat16* BgL = &g_xl[b][nt * 128][0];
    int k0 = split * 1024;
    int grp = wid >> 3, w8 = wid & 7;
    int wm = (w8 >> 2) * 64, wn = (w8 & 3) * 32;

    float acc[4][4][4] = {};

    auto stage = [&](int buf, int kk) {
        uint32_t base = sb + buf * GR_BUF;
        int r = t >> 2, c = t & 3;   // 512 threads: 128 rows x 4 16B-chunks, one each
        long go = (long)r * HWN + kk + c * 8;
        uint32_t so = r * 80 + c * 16;
        CPA16(base + so,               (const char*)(Ag + go));
        CPA16(base + GR_TILE + so,     (const char*)(BgH + go));
        CPA16(base + 2 * GR_TILE + so, (const char*)(BgL + go));
    };

    stage(0, k0);
    CPA_COMMIT();
    const int S = 32;
    for (int s = 0; s < S; s++) {
        if (s + 1 < S) { stage((s + 1) & 1, k0 + (s + 1) * 32); CPA_COMMIT(); CPA_WAIT1(); }
        else CPA_WAIT0();
        __syncthreads();
        uint32_t aBase = sb + (s & 1) * GR_BUF;
        uint32_t bBase = aBase + GR_TILE + grp * GR_TILE;
#pragma unroll
        for (int ks = 0; ks < 32; ks += 16) {
            uint32_t af[4][4], bf[4][2];
#pragma unroll
            for (int i = 0; i < 4; i++)
                ldsm4(af[i], aBase + (wm + i * 16 + (lane & 15)) * 80 + ks * 2 + (lane >> 4) * 16);
#pragma unroll
            for (int j = 0; j < 2; j++) {
                uint32_t r[4];
                ldsm4(r, bBase + (wn + j * 16 + (lane & 15)) * 80 + ks * 2 + (lane >> 4) * 16);
                bf[2 * j][0] = r[0]; bf[2 * j][1] = r[2];
                bf[2 * j + 1][0] = r[1]; bf[2 * j + 1][1] = r[3];
            }
#pragma unroll
            for (int i = 0; i < 4; i++)
#pragma unroll
                for (int j = 0; j < 4; j++) mma_bf16(acc[i][j], af[i], bf[j]);
        }
        __syncthreads();
    }

    float* dst = grp ? &g_S2p[split][b][0][0] : &g_S1p[split][b][0][0];
#pragma unroll
    for (int i = 0; i < 4; i++) {
        int m = mt * 128 + wm + i * 16 + (lane >> 2);
#pragma unroll
        for (int j = 0; j < 4; j++) {
            int n = nt * 128 + wn + j * 8 + (lane & 3) * 2;
            *(float2*)(dst + (long)m * CCH + n) = make_float2(acc[i][j][0], acc[i][j][1]);
            *(float2*)(dst + (long)(m + 8) * CCH + n) = make_float2(acc[i][j][2], acc[i][j][3]);
        }
    }
}

// G[b] = sum_s (S1 + S2) + (sum_s S2)^T
__global__ __launch_bounds__(256) void reduceG_kernel() {
    __shared__ float tt[32][33];
    int jt = blockIdx.x * 32, it = blockIdx.y * 32, b = blockIdx.z;
    int lx = threadIdx.x & 31, ly = threadIdx.x >> 5;
    for (int r = ly; r < 32; r += 8) {
        float s = 0.f;
#pragma unroll
        for (int sp = 0; sp < 4; sp++) s += g_S2p[sp][b][jt + r][it + lx];
        tt[r][lx] = s;
    }
    __syncthreads();
    for (int r = ly; r < 32; r += 8) {
        float s = tt[lx][r];
#pragma unroll
        for (int sp = 0; sp < 4; sp++)
            s += g_S1p[sp][b][it + r][jt + lx] + g_S2p[sp][b][it + r][jt + lx];
        g_G[b][it + r][jt + lx] = s;
    }
}

// ================= cov (+mean fused) =================
__global__ void cov_kernel() {
    int c = blockIdx.x, t = threadIdx.x;
    float mt_ = 0.f;
#pragma unroll
    for (int b = 0; b < BATCH; b++) mt_ += g_s[b][t];
    mt_ *= INV_NPOS;
    __shared__ float mc_sh;
    if (t == c) mc_sh = mt_;
    __syncthreads();
    float s = 0.f;
#pragma unroll
    for (int b = 0; b < BATCH; b++) s += g_G[b][c][t];
    g_Cov[c][t] = s * INV_NPOS - mc_sh * mt_;
    if (c == 0) g_mean[t] = mt_;
}

// ================= BN fold =================
__global__ void proj_kernel(
    const float* __restrict__ Wq, const float* __restrict__ bq, const float* __restrict__ gq, const float* __restrict__ beq,
    const float* __restrict__ Wk, const float* __restrict__ bk, const float* __restrict__ gk, const float* __restrict__ bek,
    const float* __restrict__ Wv, const float* __restrict__ bv, const float* __restrict__ gv, const float* __restrict__ bev) {
    int o = blockIdx.x, tp = blockIdx.y;
    const float *W, *bb, *gg, *be;
    if (tp == 0) { W = Wq; bb = bq; gg = gq; be = beq; }
    else if (tp == 1) { W = Wk; bb = bk; gg = gk; be = bek; }
    else { W = Wv; bb = bv; gg = gv; be = bev; }
    __shared__ float ws[CCH];
    int t = threadIdx.x;
    ws[t] = W[o * CCH + t];
    __syncthreads();
    float col = 0.f;
    for (int c = 0; c < CCH; c++) col += ws[c] * g_Cov[c][t];
    __shared__ float s1[256], s2[256];
    s1[t] = col * ws[t]; s2[t] = ws[t] * g_mean[t];
    __syncthreads();
    for (int off = 128; off > 0; off >>= 1) {
        if (t < off) { s1[t] += s1[t + off]; s2[t] += s2[t + off]; }
        __syncthreads();
    }
    __shared__ float a_sh, c_sh;
    if (t == 0) {
        float var = s1[0];
        float mu = s2[0] + bb[o];
        float a = gg[o] * rsqrtf(var + EPS_BN);
        a_sh = a;
        c_sh = (bb[o] - mu) * a + be[o];
    }
    __syncthreads();
    g_A[tp][o][t] = a_sh * ws[t];
    if (t == 0) g_cvec[tp][o] = c_sh;
}

// ================= fp32 glue GEMM micro-kernel =================
__device__ __forceinline__ void mma16f(const float (*As)[65], const float (*Bs)[65],
                                       int ty, int tx, float acc[4][4]) {
#pragma unroll
    for (int kk = 0; kk < 16; kk++) {
        float a[4], b[4];
#pragma unroll
        for (int i = 0; i < 4; i++) a[i] = As[kk][ty * 4 + i];
#pragma unroll
        for (int j = 0; j < 4; j++) b[j] = Bs[kk][tx * 4 + j];
#pragma unroll
        for (int i = 0; i < 4; i++)
#pragma unroll
            for (int j = 0; j < 4; j++) acc[i][j] += a[i] * b[j];
    }
}

// T1_b = G_b * Ak^T (NT)
__global__ void t1_kernel() {
    int b = blockIdx.z;
    int rowBase = blockIdx.y * 64, colBase = blockIdx.x * 64;
    __shared__ float As[16][65], Bs[16][65];
    int t = threadIdx.x, tx = t & 15, ty = t >> 4;
    int r = t >> 2, kseg = (t & 3) * 4;
    float acc[4][4] = {};
    const float* A = &g_G[b][0][0];
    const float* B = &g_A[1][0][0];
    for (int k0 = 0; k0 < CCH; k0 += 16) {
        float4 av = *(const float4*)(A + (rowBase + r) * CCH + k0 + kseg);
        float4 bv = *(const float4*)(B + (colBase + r) * CCH + k0 + kseg);
        As[kseg + 0][r] = av.x; As[kseg + 1][r] = av.y; As[kseg + 2][r] = av.z; As[kseg + 3][r] = av.w;
        Bs[kseg + 0][r] = bv.x; Bs[kseg + 1][r] = bv.y; Bs[kseg + 2][r] = bv.z; Bs[kseg + 3][r] = bv.w;
        __syncthreads();
        mma16f(As, Bs, ty, tx, acc);
        __syncthreads();
    }
#pragma unroll
    for (int i = 0; i < 4; i++)
#pragma unroll
        for (int j = 0; j < 4; j++)
            g_T1[b][rowBase + ty * 4 + i][colBase + tx * 4 + j] = acc[i][j];
}

// M_b = Av * T1_b + rank-1 corrections (uw fused in prologue)
__global__ void m_kernel() {
    int b = blockIdx.z;
    int rowBase = blockIdx.y * 64, colBase = blockIdx.x * 64;
    __shared__ float As[16][65], Bs[16][65];
    __shared__ float ss[CCH], su[64], sw[64];
    int t = threadIdx.x, tx = t & 15, ty = t >> 4;
    int ar = t >> 2, akseg = (t & 3) * 4;
    int bkk = t >> 4, bcc = (t & 15) * 4;
    ss[t] = g_s[b][t];
    __syncthreads();
    if (t < 64) {            // u = Av * s for this block's rows
        float a = 0.f;
        const float* row = &g_A[2][rowBase + t][0];
        for (int c = 0; c < CCH; c++) a += row[c] * ss[c];
        su[t] = a;
    } else if (t < 128) {    // w = Ak * s for this block's cols
        int j = t - 64;
        float a = 0.f;
        const float* row = &g_A[1][colBase + j][0];
        for (int c = 0; c < CCH; c++) a += row[c] * ss[c];
        sw[j] = a;
    }
    float acc[4][4] = {};
    const float* A = &g_A[2][0][0];
    const float* B = &g_T1[b][0][0];
    for (int k0 = 0; k0 < CCH; k0 += 16) {
        float4 av = *(const float4*)(A + (rowBase + ar) * CCH + k0 + akseg);
        float4 bv = *(const float4*)(B + (k0 + bkk) * CCH + colBase + bcc);
        As[akseg + 0][ar] = av.x; As[akseg + 1][ar] = av.y; As[akseg + 2][ar] = av.z; As[akseg + 3][ar] = av.w;
        Bs[bkk][bcc + 0] = bv.x; Bs[bkk][bcc + 1] = bv.y; Bs[bkk][bcc + 2] = bv.z; Bs[bkk][bcc + 3] = bv.w;
        __syncthreads();
        mma16f(As, Bs, ty, tx, acc);
        __syncthreads();
    }
#pragma unroll
    for (int i = 0; i < 4; i++) {
        int ri = rowBase + ty * 4 + i;
        float u = su[ty * 4 + i], cv = g_cvec[2][ri];
#pragma unroll
        for (int j = 0; j < 4; j++) {
            int cj = colBase + tx * 4 + j;
            float ck = g_cvec[1][cj];
            g_M[b][ri][cj] = acc[i][j] + u * ck + cv * sw[tx * 4 + j] + 4096.0f * cv * ck;
        }
    }
}

// P_b = scale * M_b * Aq -> written as bf16 hi/lo; d fused (colBase==0 blocks)
__global__ void p_kernel() {
    int b = blockIdx.z;
    int rowBase = blockIdx.y * 64, colBase = blockIdx.x * 64;
    __shared__ float As[16][65], Bs[16][65];
    __shared__ float cqs[CCH];
    int t = threadIdx.x, tx = t & 15, ty = t >> 4;
    int ar = t >> 2, akseg = (t & 3) * 4;
    int bkk = t >> 4, bcc = (t & 15) * 4;
    cqs[t] = g_cvec[0][t];
    float acc[4][4] = {};
    float dacc[4] = {};
    const float* A = &g_M[b][0][0];
    const float* B = &g_A[0][0][0];
    for (int k0 = 0; k0 < CCH; k0 += 16) {
        float4 av = *(const float4*)(A + (rowBase + ar) * CCH + k0 + akseg);
        float4 bv = *(const float4*)(B + (k0 + bkk) * CCH + colBase + bcc);
        As[akseg + 0][ar] = av.x; As[akseg + 1][ar] = av.y; As[akseg + 2][ar] = av.z; As[akseg + 3][ar] = av.w;
        Bs[bkk][bcc + 0] = bv.x; Bs[bkk][bcc + 1] = bv.y; Bs[bkk][bcc + 2] = bv.z; Bs[bkk][bcc + 3] = bv.w;
        __syncthreads();
        mma16f(As, Bs, ty, tx, acc);
        if (tx == 0) {  // d = M * cq partial (full k covered by the loop)
#pragma unroll
            for (int kk = 0; kk < 16; kk++) {
                float cq = cqs[k0 + kk];
#pragma unroll
                for (int i = 0; i < 4; i++) dacc[i] += As[kk][ty * 4 + i] * cq;
            }
        }
        __syncthreads();
    }
#pragma unroll
    for (int i = 0; i < 4; i++) {
        int ri = rowBase + ty * 4 + i;
#pragma unroll
        for (int j = 0; j < 4; j++) {
            int cj = colBase + tx * 4 + j;
            float v = acc[i][j] * SCALE;
            __nv_bfloat16 h = __float2bfloat16(v);
            g_Ph[b][ri][cj] = h;
            g_Pl[b][ri][cj] = __float2bfloat16(v - __bfloat162float(h));
        }
        if (blockIdx.x == 0 && tx == 0) g_d[b][ri] = dacc[i] * SCALE;
    }
}

// ================= out via mma.sync: out = Ph Xh + Ph Xl + Pl Xh =================
#define OB_STRIDE 272   // bytes per B smem row (128 bf16 + 8 pad)
#define OU_AH 0
#define OU_AL 10240
#define OU_BH 20480
#define OU_BL (20480 + 32 * OB_STRIDE)
#define OU_BUF (20480 + 2 * 32 * OB_STRIDE)   // 37888
#define OU_SMEM (2 * OU_BUF)                  // 75776

__global__ __launch_bounds__(256) void out_mma_kernel(float* __restrict__ out) {
    extern __shared__ char smem[];
    uint32_t sb = smem_u32(smem);
    int t = threadIdx.x, lane = t & 31, wid = t >> 5;
    int pt = blockIdx.x, mt = blockIdx.y, b = blockIdx.z;
    int wm = (wid >> 2) * 64, wn = (wid & 3) * 32;
    const __nv_bfloat16* Ah = &g_Ph[b][mt * 128][0];
    const __nv_bfloat16* Al = &g_Pl[b][mt * 128][0];
    const __nv_bfloat16* Bh = &g_xh[b][0][pt * 128];
    const __nv_bfloat16* Bl = &g_xl[b][0][pt * 128];

    float acc[4][4][4] = {};

    auto stage = [&](int buf, int kk) {
        uint32_t base = sb + buf * OU_BUF;
#pragma unroll
        for (int i = t; i < 512; i += 256) {   // A tiles: 128 rows x 4 chunks
            int r = i >> 2, c = i & 3;
            CPA16(base + OU_AH + r * 80 + c * 16, (const char*)(Ah + (long)r * CCH + kk + c * 8));
            CPA16(base + OU_AL + r * 80 + c * 16, (const char*)(Al + (long)r * CCH + kk + c * 8));
        }
#pragma unroll
        for (int i = t; i < 512; i += 256) {   // B tiles: 32 rows (k=c') x 16 chunks (n=p)
            int r = i >> 4, c = i & 15;
            CPA16(base + OU_BH + r * OB_STRIDE + c * 16, (const char*)(Bh + (long)(kk + r) * HWN + c * 8));
            CPA16(base + OU_BL + r * OB_STRIDE + c * 16, (const char*)(Bl + (long)(kk + r) * HWN + c * 8));
        }
    };

    stage(0, 0);
    CPA_COMMIT();
    const int S = 8;  // K=256 / 32
    for (int s = 0; s < S; s++) {
        if (s + 1 < S) { stage((s + 1) & 1, (s + 1) * 32); CPA_COMMIT(); CPA_WAIT1(); }
        else CPA_WAIT0();
        __syncthreads();
        uint32_t base = sb + (s & 1) * OU_BUF;
#pragma unroll
        for (int ks = 0; ks < 32; ks += 16) {
            uint32_t afh[4][4], afl[4][4], bfh[4][2], bfl[4][2];
#pragma unroll
            for (int i = 0; i < 4; i++) {
                uint32_t ao = (wm + i * 16 + (lane & 15)) * 80 + ks * 2 + (lane >> 4) * 16;
                ldsm4(afh[i], base + OU_AH + ao);
                ldsm4(afl[i], base + OU_AL + ao);
            }
#pragma unroll
            for (int j = 0; j < 2; j++) {
                uint32_t bo = (ks + (lane & 15)) * OB_STRIDE + (wn + j * 16 + (lane >> 4) * 8) * 2;
                uint32_t r[4];
                ldsm4t(r, base + OU_BH + bo);
                bfh[2 * j][0] = r[0]; bfh[2 * j][1] = r[1];
                bfh[2 * j + 1][0] = r[2]; bfh[2 * j + 1][1] = r[3];
                ldsm4t(r, base + OU_BL + bo);
                bfl[2 * j][0] = r[0]; bfl[2 * j][1] = r[1];
                bfl[2 * j + 1][0] = r[2]; bfl[2 * j + 1][1] = r[3];
            }
#pragma unroll
            for (int i = 0; i < 4; i++)
#pragma unroll
                for (int j = 0; j < 4; j++) {
                    mma_bf16(acc[i][j], afh[i], bfh[j]);
                    mma_bf16(acc[i][j], afh[i], bfl[j]);
                    mma_bf16(acc[i][j], afl[i], bfh[j]);
                }
        }
        __syncthreads();
    }

#pragma unroll
    for (int i = 0; i < 4; i++) {
        int m = mt * 128 + wm + i * 16 + (lane >> 2);
        float d0 = g_d[b][m], d1 = g_d[b][m + 8];
        float* O0 = out + ((long)(b * CCH + m)) * HWN + pt * 128;
        float* O1 = O0 + 8L * HWN;
#pragma unroll
        for (int j = 0; j < 4; j++) {
            int n = wn + j * 8 + (lane & 3) * 2;
            *(float2*)(O0 + n) = make_float2(acc[i][j][0] + d0, acc[i][j][1] + d0);
            *(float2*)(O1 + n) = make_float2(acc[i][j][2] + d1, acc[i][j][3] + d1);
        }
    }
}

// ================= launch =================
extern "C" void kernel_launch(void* const* d_in, const int* in_sizes, int n_in,
                              void* d_out, int out_size) {
    const float* x = (const float*)d_in[0];

    static bool attr_done = false;
    if (!attr_done) {
        cudaFuncSetAttribute(gram_mma_kernel, cudaFuncAttributeMaxDynamicSharedMemorySize, GR_SMEM);
        cudaFuncSetAttribute(out_mma_kernel,  cudaFuncAttributeMaxDynamicSharedMemorySize, OU_SMEM);
        attr_done = true;
    }

    prep_kernel<<<dim3(CCH, BATCH), 256>>>(x);
    gram_mma_kernel<<<dim3(4, 4, BATCH), 512, GR_SMEM>>>();
    reduceG_kernel<<<dim3(8, 8, BATCH), 256>>>();
    cov_kernel<<<CCH, 256>>>();
    proj_kernel<<<dim3(CCH, 3), 256>>>(
        (const float*)d_in[1], (const float*)d_in[2], (const float*)d_in[3], (const float*)d_in[4],
        (const float*)d_in[5], (const float*)d_in[6], (const float*)d_in[7], (const float*)d_in[8],
        (const float*)d_in[9], (const float*)d_in[10], (const float*)d_in[11], (const float*)d_in[12]);
    t1_kernel<<<dim3(4, 4, BATCH), 256>>>();
    m_kernel<<<dim3(4, 4, BATCH), 256>>>();
    p_kernel<<<dim3(4, 4, BATCH), 256>>>();
    out_mma_kernel<<<dim3(32, 2, BATCH), 256, OU_SMEM>>>((float*)d_out);
}